// round 1
// baseline (speedup 1.0000x reference)
#include <cuda_runtime.h>
#include <cstdint>

#define HH 256
#define WW 256
#define NB 8
#define CO 64
#define CIN 256
#define CHID 16
#define PLANE (HH*WW)

// per-sample modulated+demodulated conv weights, tf32-rounded, [b][tap][o][i]
__device__ float g_wmod[NB*9*CO*CO];

__device__ __forceinline__ float tf32r(float v) {
    unsigned r;
    asm volatile("cvt.rna.tf32.f32 %0, %1;" : "=r"(r) : "f"(v));
    return __uint_as_float(r);
}

// ---------------------------------------------------------------------------
// Kernel 1: style MLP + weight modulation/demodulation (one block per sample)
// ---------------------------------------------------------------------------
__global__ void style_kernel(const float* __restrict__ vec,
                             const float* __restrict__ w1,
                             const float* __restrict__ w2,
                             const float* __restrict__ wconv) {
    const int b = blockIdx.x;
    const int tid = threadIdx.x;
    __shared__ float sv[CIN];
    __shared__ float sh[CHID];
    __shared__ float ss[CO];

    sv[tid] = vec[b*CIN + tid];          // blockDim.x == 256 == CIN
    __syncthreads();

    if (tid < CHID) {
        float acc = 0.f;
        #pragma unroll 8
        for (int c = 0; c < CIN; ++c) acc += sv[c] * w1[tid*CIN + c];
        sh[tid] = (acc > 0.f) ? acc : 0.1f * acc;   // LeakyReLU(0.1)
    }
    __syncthreads();

    if (tid < CO) {
        float acc = 0.f;
        #pragma unroll
        for (int j = 0; j < CHID; ++j) acc += sh[j] * w2[tid*CHID + j];
        ss[tid] = acc + 1.0f;            // sty + 1
    }
    __syncthreads();

    const int warp = tid >> 5, lane = tid & 31;
    for (int o = warp; o < CO; o += 8) {
        float acc = 0.f;
        for (int idx = lane; idx < 576; idx += 32) {
            float v = wconv[o*576 + idx] * ss[idx / 9];
            acc += v * v;
        }
        #pragma unroll
        for (int s = 16; s; s >>= 1) acc += __shfl_xor_sync(0xffffffffu, acc, s);
        const float d = rsqrtf(acc + 1e-8f);
        for (int idx = lane; idx < 576; idx += 32) {
            int i = idx / 9, t = idx % 9;
            float v = wconv[o*576 + idx] * ss[i] * d;
            g_wmod[((b*9 + t)*CO + o)*CO + i] = tf32r(v);
        }
    }
}

// ---------------------------------------------------------------------------
// Kernel 2: fused ChanNorm + modulated 3x3 conv (tf32 mma.sync) + residual
// CTA tile: 4 rows x 64 cols x 64 out-channels of one sample.
// smem: xs[6][66][68] (halo tile, ch-stride 68 -> conflict-free MMA frags),
//       wt[64][68] (current tap weights), sg/sb (affine params)
// ---------------------------------------------------------------------------
#define XS_STRIDE 68
#define XS_FLOATS (6*66*XS_STRIDE)
#define WT_FLOATS (64*XS_STRIDE)

__device__ __forceinline__ void mma_tf32(float c[4], const unsigned a[4],
                                         const unsigned bb[2]) {
    asm volatile(
        "mma.sync.aligned.m16n8k8.row.col.f32.tf32.tf32.f32 "
        "{%0,%1,%2,%3}, {%4,%5,%6,%7}, {%8,%9}, {%0,%1,%2,%3};\n"
        : "+f"(c[0]), "+f"(c[1]), "+f"(c[2]), "+f"(c[3])
        : "r"(a[0]), "r"(a[1]), "r"(a[2]), "r"(a[3]),
          "r"(bb[0]), "r"(bb[1]));
}

__global__ __launch_bounds__(256, 1)
void conv_kernel(const float* __restrict__ x,
                 const float* __restrict__ gaff,
                 const float* __restrict__ baff,
                 float* __restrict__ out) {
    extern __shared__ float sm[];
    float* xs  = sm;                       // [6][66][68]
    float* wt  = sm + XS_FLOATS;           // [64][68]
    float* sg  = wt + WT_FLOATS;           // [64]
    float* sbv = sg + 64;                  // [64]

    const int tx = blockIdx.x, ty = blockIdx.y, b = blockIdx.z;
    const int x0 = tx * 64, y0 = ty * 4;
    const int tid = threadIdx.x;

    if (tid < 64) { sg[tid] = gaff[tid]; sbv[tid] = baff[tid]; }

    const float* xb = x + (size_t)b * CO * PLANE;

    // ---- load halo tile (coalesced on gx; 4-way STS conflicts acceptable) ----
    for (int idx = tid; idx < 6*66*64; idx += 256) {
        int c  = idx % 66;
        int r  = (idx / 66) % 6;
        int ch = idx / (66*6);
        int gy = y0 - 1 + r, gx = x0 - 1 + c;
        float v = 0.f;
        if (gy >= 0 && gy < HH && gx >= 0 && gx < WW)
            v = xb[(size_t)ch * PLANE + gy*WW + gx];
        xs[(r*66 + c)*XS_STRIDE + ch] = v;
    }
    __syncthreads();

    // ---- per-pixel ChanNorm over 64 channels, tf32-round in place ----
    for (int pix = tid; pix < 6*66; pix += 256) {
        int r = pix / 66, c = pix % 66;
        int gy = y0 - 1 + r, gx = x0 - 1 + c;
        float* p = &xs[(r*66 + c)*XS_STRIDE];
        if (gy < 0 || gy >= HH || gx < 0 || gx >= WW) {
            #pragma unroll 8
            for (int i = 0; i < 64; ++i) p[i] = 0.f;   // zero-pad AFTER norm
        } else {
            float s = 0.f, s2 = 0.f;
            #pragma unroll 8
            for (int i = 0; i < 64; ++i) { float v = p[i]; s += v; s2 += v*v; }
            float mean = s * (1.f/64.f);
            float var  = s2 * (1.f/64.f) - mean*mean;
            float rstd = rsqrtf(var + 1e-5f);
            #pragma unroll 8
            for (int i = 0; i < 64; ++i)
                p[i] = tf32r((p[i] - mean) * rstd * sg[i] + sbv[i]);
        }
    }
    // first sync inside the tap loop orders norm-writes before MMA reads

    const int warp = tid >> 5, lane = tid & 31;
    const int wrow = warp >> 1;            // 0..3 : output row within tile
    const int wcol = (warp & 1) * 32;      // 0/32 : output col base
    const int gq = lane >> 2, tq = lane & 3;

    float acc[2][8][4];
    #pragma unroll
    for (int mt = 0; mt < 2; ++mt)
        #pragma unroll
        for (int nt = 0; nt < 8; ++nt)
            #pragma unroll
            for (int j = 0; j < 4; ++j) acc[mt][nt][j] = 0.f;

    const float* wmod_b = g_wmod + (size_t)b * 9 * CO * CO;

    for (int tap = 0; tap < 9; ++tap) {
        __syncthreads();                       // wt readers done / norm done
        const float* wsrc = wmod_b + tap * CO * CO;
        for (int idx = tid; idx < 4096; idx += 256)
            wt[(idx >> 6)*XS_STRIDE + (idx & 63)] = wsrc[idx];
        __syncthreads();

        const int ky = tap / 3, kx = tap % 3;
        const float* arow = &xs[((wrow + ky)*66 + wcol + kx)*XS_STRIDE];

        #pragma unroll
        for (int kt = 0; kt < 8; ++kt) {
            const int kb = kt * 8;
            unsigned bfr[8][2];
            #pragma unroll
            for (int nt = 0; nt < 8; ++nt) {
                const float* wp = &wt[(nt*8 + gq)*XS_STRIDE + kb + tq];
                bfr[nt][0] = __float_as_uint(wp[0]);
                bfr[nt][1] = __float_as_uint(wp[4]);
            }
            #pragma unroll
            for (int mt = 0; mt < 2; ++mt) {
                unsigned afr[4];
                const float* ap = arow + (mt*16 + gq)*XS_STRIDE + kb + tq;
                afr[0] = __float_as_uint(ap[0]);
                afr[1] = __float_as_uint(ap[8*XS_STRIDE]);
                afr[2] = __float_as_uint(ap[4]);
                afr[3] = __float_as_uint(ap[8*XS_STRIDE + 4]);
                #pragma unroll
                for (int nt = 0; nt < 8; ++nt)
                    mma_tf32(acc[mt][nt], afr, bfr[nt]);
            }
        }
    }

    // ---- epilogue: + residual x, store ----
    float* ob = out + (size_t)b * CO * PLANE;
    const int py = y0 + wrow;
    #pragma unroll
    for (int mt = 0; mt < 2; ++mt) {
        #pragma unroll
        for (int j2 = 0; j2 < 2; ++j2) {
            const int px = x0 + wcol + mt*16 + gq + j2*8;
            const size_t base = (size_t)py * WW + px;
            #pragma unroll
            for (int nt = 0; nt < 8; ++nt) {
                const int o0 = nt*8 + tq*2;
                const size_t i0 = (size_t)o0 * PLANE + base;
                ob[i0]         = xb[i0]         + acc[mt][nt][j2*2 + 0];
                ob[i0 + PLANE] = xb[i0 + PLANE] + acc[mt][nt][j2*2 + 1];
            }
        }
    }
}

// ---------------------------------------------------------------------------
extern "C" void kernel_launch(void* const* d_in, const int* in_sizes, int n_in,
                              void* d_out, int out_size) {
    (void)in_sizes; (void)n_in; (void)out_size;
    const float* x     = (const float*)d_in[0];
    const float* vec   = (const float*)d_in[1];
    const float* gaff  = (const float*)d_in[2];
    const float* baff  = (const float*)d_in[3];
    const float* w1    = (const float*)d_in[4];
    const float* w2    = (const float*)d_in[5];
    const float* wconv = (const float*)d_in[6];
    float* out = (float*)d_out;

    style_kernel<<<NB, 256>>>(vec, w1, w2, wconv);

    const size_t smem = (XS_FLOATS + WT_FLOATS + 128) * sizeof(float);
    cudaFuncSetAttribute(conv_kernel,
                         cudaFuncAttributeMaxDynamicSharedMemorySize,
                         (int)smem);
    dim3 grid(WW/64, HH/4, NB);
    conv_kernel<<<grid, 256, smem>>>(x, gaff, baff, out);
}

// round 2
// speedup vs baseline: 1.0029x; 1.0029x over previous
#include <cuda_runtime.h>
#include <cstdint>

#define HH 256
#define WW 256
#define NB 8
#define CO 64
#define CIN 256
#define CHID 16
#define PLANE (HH*WW)

// per-sample modulated+demodulated conv weights, tf32-rounded, [b][tap][o][i]
__device__ float g_wmod[NB*9*CO*CO];

__device__ __forceinline__ float tf32r(float v) {
    unsigned r;
    asm volatile("cvt.rna.tf32.f32 %0, %1;" : "=r"(r) : "f"(v));
    return __uint_as_float(r);
}

// ---------------------------------------------------------------------------
// Kernel 1: style MLP + weight modulation/demodulation (one block per sample)
// ---------------------------------------------------------------------------
__global__ void style_kernel(const float* __restrict__ vec,
                             const float* __restrict__ w1,
                             const float* __restrict__ w2,
                             const float* __restrict__ wconv) {
    const int b = blockIdx.x;
    const int tid = threadIdx.x;
    __shared__ float sv[CIN];
    __shared__ float sh[CHID];
    __shared__ float ss[CO];

    sv[tid] = vec[b*CIN + tid];          // blockDim.x == 256 == CIN
    __syncthreads();

    if (tid < CHID) {
        float acc = 0.f;
        #pragma unroll 8
        for (int c = 0; c < CIN; ++c) acc += sv[c] * w1[tid*CIN + c];
        sh[tid] = (acc > 0.f) ? acc : 0.1f * acc;   // LeakyReLU(0.1)
    }
    __syncthreads();

    if (tid < CO) {
        float acc = 0.f;
        #pragma unroll
        for (int j = 0; j < CHID; ++j) acc += sh[j] * w2[tid*CHID + j];
        ss[tid] = acc + 1.0f;            // sty + 1
    }
    __syncthreads();

    const int warp = tid >> 5, lane = tid & 31;
    for (int o = warp; o < CO; o += 8) {
        float acc = 0.f;
        for (int idx = lane; idx < 576; idx += 32) {
            float v = wconv[o*576 + idx] * ss[idx / 9];
            acc += v * v;
        }
        #pragma unroll
        for (int s = 16; s; s >>= 1) acc += __shfl_xor_sync(0xffffffffu, acc, s);
        const float d = rsqrtf(acc + 1e-8f);
        for (int idx = lane; idx < 576; idx += 32) {
            int i = idx / 9, t = idx % 9;
            float v = wconv[o*576 + idx] * ss[i] * d;
            g_wmod[((b*9 + t)*CO + o)*CO + i] = tf32r(v);
        }
    }
}

// ---------------------------------------------------------------------------
// Kernel 2: fused ChanNorm + modulated 3x3 conv (tf32 mma.sync) + residual
// CTA tile: 4 rows x 64 cols x 64 out-channels of one sample.
// smem: xs[6][66][68] (halo tile, ch-stride 68 -> conflict-free MMA frags),
//       wt[64][68] (current tap weights), sg/sb (affine params)
// ---------------------------------------------------------------------------
#define XS_STRIDE 68
#define XS_FLOATS (6*66*XS_STRIDE)
#define WT_FLOATS (64*XS_STRIDE)

__device__ __forceinline__ void mma_tf32(float c[4], const unsigned a[4],
                                         const unsigned bb[2]) {
    asm volatile(
        "mma.sync.aligned.m16n8k8.row.col.f32.tf32.tf32.f32 "
        "{%0,%1,%2,%3}, {%4,%5,%6,%7}, {%8,%9}, {%0,%1,%2,%3};\n"
        : "+f"(c[0]), "+f"(c[1]), "+f"(c[2]), "+f"(c[3])
        : "r"(a[0]), "r"(a[1]), "r"(a[2]), "r"(a[3]),
          "r"(bb[0]), "r"(bb[1]));
}

__global__ __launch_bounds__(256, 1)
void conv_kernel(const float* __restrict__ x,
                 const float* __restrict__ gaff,
                 const float* __restrict__ baff,
                 float* __restrict__ out) {
    extern __shared__ float sm[];
    float* xs  = sm;                       // [6][66][68]
    float* wt  = sm + XS_FLOATS;           // [64][68]
    float* sg  = wt + WT_FLOATS;           // [64]
    float* sbv = sg + 64;                  // [64]

    const int tx = blockIdx.x, ty = blockIdx.y, b = blockIdx.z;
    const int x0 = tx * 64, y0 = ty * 4;
    const int tid = threadIdx.x;

    if (tid < 64) { sg[tid] = gaff[tid]; sbv[tid] = baff[tid]; }

    const float* xb = x + (size_t)b * CO * PLANE;

    // ---- load halo tile (coalesced on gx; 4-way STS conflicts acceptable) ----
    for (int idx = tid; idx < 6*66*64; idx += 256) {
        int c  = idx % 66;
        int r  = (idx / 66) % 6;
        int ch = idx / (66*6);
        int gy = y0 - 1 + r, gx = x0 - 1 + c;
        float v = 0.f;
        if (gy >= 0 && gy < HH && gx >= 0 && gx < WW)
            v = xb[(size_t)ch * PLANE + gy*WW + gx];
        xs[(r*66 + c)*XS_STRIDE + ch] = v;
    }
    __syncthreads();

    // ---- per-pixel ChanNorm over 64 channels, tf32-round in place ----
    for (int pix = tid; pix < 6*66; pix += 256) {
        int r = pix / 66, c = pix % 66;
        int gy = y0 - 1 + r, gx = x0 - 1 + c;
        float* p = &xs[(r*66 + c)*XS_STRIDE];
        if (gy < 0 || gy >= HH || gx < 0 || gx >= WW) {
            #pragma unroll 8
            for (int i = 0; i < 64; ++i) p[i] = 0.f;   // zero-pad AFTER norm
        } else {
            float s = 0.f, s2 = 0.f;
            #pragma unroll 8
            for (int i = 0; i < 64; ++i) { float v = p[i]; s += v; s2 += v*v; }
            float mean = s * (1.f/64.f);
            float var  = s2 * (1.f/64.f) - mean*mean;
            float rstd = rsqrtf(var + 1e-5f);
            #pragma unroll 8
            for (int i = 0; i < 64; ++i)
                p[i] = tf32r((p[i] - mean) * rstd * sg[i] + sbv[i]);
        }
    }
    // first sync inside the tap loop orders norm-writes before MMA reads

    const int warp = tid >> 5, lane = tid & 31;
    const int wrow = warp >> 1;            // 0..3 : output row within tile
    const int wcol = (warp & 1) * 32;      // 0/32 : output col base
    const int gq = lane >> 2, tq = lane & 3;

    float acc[2][8][4];
    #pragma unroll
    for (int mt = 0; mt < 2; ++mt)
        #pragma unroll
        for (int nt = 0; nt < 8; ++nt)
            #pragma unroll
            for (int j = 0; j < 4; ++j) acc[mt][nt][j] = 0.f;

    const float* wmod_b = g_wmod + (size_t)b * 9 * CO * CO;

    for (int tap = 0; tap < 9; ++tap) {
        __syncthreads();                       // wt readers done / norm done
        const float* wsrc = wmod_b + tap * CO * CO;
        for (int idx = tid; idx < 4096; idx += 256)
            wt[(idx >> 6)*XS_STRIDE + (idx & 63)] = wsrc[idx];
        __syncthreads();

        const int ky = tap / 3, kx = tap % 3;
        const float* arow = &xs[((wrow + ky)*66 + wcol + kx)*XS_STRIDE];

        #pragma unroll
        for (int kt = 0; kt < 8; ++kt) {
            const int kb = kt * 8;
            unsigned bfr[8][2];
            #pragma unroll
            for (int nt = 0; nt < 8; ++nt) {
                const float* wp = &wt[(nt*8 + gq)*XS_STRIDE + kb + tq];
                bfr[nt][0] = __float_as_uint(wp[0]);
                bfr[nt][1] = __float_as_uint(wp[4]);
            }
            #pragma unroll
            for (int mt = 0; mt < 2; ++mt) {
                unsigned afr[4];
                const float* ap = arow + (mt*16 + gq)*XS_STRIDE + kb + tq;
                afr[0] = __float_as_uint(ap[0]);
                afr[1] = __float_as_uint(ap[8*XS_STRIDE]);
                afr[2] = __float_as_uint(ap[4]);
                afr[3] = __float_as_uint(ap[8*XS_STRIDE + 4]);
                #pragma unroll
                for (int nt = 0; nt < 8; ++nt)
                    mma_tf32(acc[mt][nt], afr, bfr[nt]);
            }
        }
    }

    // ---- epilogue: + residual x, store ----
    float* ob = out + (size_t)b * CO * PLANE;
    const int py = y0 + wrow;
    #pragma unroll
    for (int mt = 0; mt < 2; ++mt) {
        #pragma unroll
        for (int j2 = 0; j2 < 2; ++j2) {
            const int px = x0 + wcol + mt*16 + gq + j2*8;
            const size_t base = (size_t)py * WW + px;
            #pragma unroll
            for (int nt = 0; nt < 8; ++nt) {
                const int o0 = nt*8 + tq*2;
                const size_t i0 = (size_t)o0 * PLANE + base;
                ob[i0]         = xb[i0]         + acc[mt][nt][j2*2 + 0];
                ob[i0 + PLANE] = xb[i0 + PLANE] + acc[mt][nt][j2*2 + 1];
            }
        }
    }
}

// ---------------------------------------------------------------------------
extern "C" void kernel_launch(void* const* d_in, const int* in_sizes, int n_in,
                              void* d_out, int out_size) {
    (void)in_sizes; (void)n_in; (void)out_size;
    const float* x     = (const float*)d_in[0];
    const float* vec   = (const float*)d_in[1];
    const float* gaff  = (const float*)d_in[2];
    const float* baff  = (const float*)d_in[3];
    const float* w1    = (const float*)d_in[4];
    const float* w2    = (const float*)d_in[5];
    const float* wconv = (const float*)d_in[6];
    float* out = (float*)d_out;

    style_kernel<<<NB, 256>>>(vec, w1, w2, wconv);

    const size_t smem = (XS_FLOATS + WT_FLOATS + 128) * sizeof(float);
    cudaFuncSetAttribute(conv_kernel,
                         cudaFuncAttributeMaxDynamicSharedMemorySize,
                         (int)smem);
    dim3 grid(WW/64, HH/4, NB);
    conv_kernel<<<grid, 256, smem>>>(x, gaff, baff, out);
}

// round 4
// speedup vs baseline: 3.5530x; 3.5429x over previous
#include <cuda_runtime.h>
#include <cuda_fp16.h>
#include <cstdint>

#define HH 256
#define WW 256
#define NB 8
#define PLANE (HH*WW)
#define CIN 256
#define CHID 16

// per-sample demodulated conv weights, fp16 half2-packed, dense:
// [b][tap][o][32 words]  (word ip = channels 2ip, 2ip+1)
__device__ unsigned g_wmodh[NB * 9 * 64 * 32];

// ---------------------------------------------------------------------------
// Kernel 1: style MLP + weight modulation/demodulation -> fp16 packed weights
// ---------------------------------------------------------------------------
__global__ void style_kernel(const float* __restrict__ vec,
                             const float* __restrict__ w1,
                             const float* __restrict__ w2,
                             const float* __restrict__ wconv) {
    const int b = blockIdx.x, tid = threadIdx.x;
    __shared__ float sv[CIN], sh[CHID], ss[64];
    sv[tid] = vec[b*CIN + tid];
    __syncthreads();
    if (tid < CHID) {
        float acc = 0.f;
        #pragma unroll 8
        for (int c = 0; c < CIN; ++c) acc += sv[c] * w1[tid*CIN + c];
        sh[tid] = (acc > 0.f) ? acc : 0.1f * acc;     // LeakyReLU(0.1)
    }
    __syncthreads();
    if (tid < 64) {
        float acc = 0.f;
        #pragma unroll
        for (int j = 0; j < CHID; ++j) acc += sh[j] * w2[tid*CHID + j];
        ss[tid] = acc + 1.0f;                          // sty + 1
    }
    __syncthreads();
    const int warp = tid >> 5, lane = tid & 31;
    for (int o = warp; o < 64; o += 8) {
        float acc = 0.f;
        for (int idx = lane; idx < 576; idx += 32) {
            float v = wconv[o*576 + idx] * ss[idx / 9];
            acc += v * v;
        }
        #pragma unroll
        for (int s = 16; s; s >>= 1) acc += __shfl_xor_sync(0xffffffffu, acc, s);
        const float d = rsqrtf(acc + 1e-8f);
        for (int m = lane; m < 288; m += 32) {
            const int ip = m / 9, t = m % 9;
            const int i0 = 2 * ip;
            float v0 = wconv[o*576 + i0*9 + t]     * ss[i0]   * d;
            float v1 = wconv[o*576 + (i0+1)*9 + t] * ss[i0+1] * d;
            __half2 h = __floats2half2_rn(v0, v1);
            g_wmodh[(size_t)((b*9 + t)*64 + o)*32 + ip] = *(unsigned*)&h;
        }
    }
}

// ---------------------------------------------------------------------------
// Kernel 2: fused ChanNorm + modulated 3x3 conv (fp16 m16n8k16) + residual
// CTA tile: 8 rows x 32 cols x 64 out-ch.  8 warps, warp = one output row.
// xs layout: [pix = r*34+cc][44 words] half2 pixel-major (stride 44 words
// => 12 mod 32: A-frag LDS 12*gq + tq conflict-free; B same).
// ---------------------------------------------------------------------------
#define XW 44
#define NPX 340                          /* 10 halo rows * 34 halo cols */
#define OFF_WT (NPX*XW)                  /* 14960 words */
#define OFF_G  (OFF_WT + 64*XW)          /* +2816 */
#define OFF_B  (OFF_G + 64)
#define SMEM_WORDS (OFF_B + 64)          /* 17904 words = 71616 B */

__device__ __forceinline__ void mma_f16(float c[4],
                                        unsigned a0, unsigned a1,
                                        unsigned a2, unsigned a3,
                                        unsigned b0, unsigned b1) {
    asm volatile(
        "mma.sync.aligned.m16n8k16.row.col.f32.f16.f16.f32 "
        "{%0,%1,%2,%3}, {%4,%5,%6,%7}, {%8,%9}, {%0,%1,%2,%3};\n"
        : "+f"(c[0]), "+f"(c[1]), "+f"(c[2]), "+f"(c[3])
        : "r"(a0), "r"(a1), "r"(a2), "r"(a3), "r"(b0), "r"(b1));
}

__global__ __launch_bounds__(256, 2)
void conv_kernel(const float* __restrict__ x,
                 const float* __restrict__ gaff,
                 const float* __restrict__ baff,
                 float* __restrict__ out) {
    extern __shared__ unsigned sm[];
    unsigned* xs = sm;
    unsigned* wt = sm + OFF_WT;
    float* sg = (float*)(sm + OFF_G);
    float* sb = (float*)(sm + OFF_B);

    const int tid = threadIdx.x, warp = tid >> 5, lane = tid & 31;
    const int gq = lane >> 2, tq = lane & 3;
    const int x0 = blockIdx.x * 32, y0 = blockIdx.y * 8, b = blockIdx.z;
    const float* xb = x + (size_t)b * 64 * PLANE;

    if (tid < 64) { sg[tid] = gaff[tid]; sb[tid] = baff[tid]; }
    __syncthreads();

    // ---- ChanNorm halo tile -> fp16 half2 smem ----
    for (int p = tid; p < NPX; p += 256) {
        const int r = p / 34, cc = p % 34;
        const int gy = y0 - 1 + r, gx = x0 - 1 + cc;
        unsigned* dst = xs + p * XW;
        if (gy >= 0 && gy < HH && gx >= 0 && gx < WW) {
            const float* px = xb + (size_t)gy * WW + gx;
            float v[64], s = 0.f, s2 = 0.f;
            #pragma unroll
            for (int c = 0; c < 64; ++c) v[c] = px[(size_t)c * PLANE];
            #pragma unroll
            for (int c = 0; c < 64; ++c) { s += v[c]; s2 += v[c]*v[c]; }
            const float mean = s * (1.f/64.f);
            const float rstd = rsqrtf(s2 * (1.f/64.f) - mean*mean + 1e-5f);
            #pragma unroll
            for (int w = 0; w < 32; ++w) {
                float n0 = (v[2*w]   - mean) * rstd * sg[2*w]   + sb[2*w];
                float n1 = (v[2*w+1] - mean) * rstd * sg[2*w+1] + sb[2*w+1];
                __half2 h = __floats2half2_rn(n0, n1);
                dst[w] = *(unsigned*)&h;
            }
        } else {
            #pragma unroll
            for (int w = 0; w < 32; ++w) dst[w] = 0u;   // pad AFTER norm
        }
    }

    // ---- prefetch tap-0 weights into registers ----
    const unsigned* wbase = g_wmodh + (size_t)(b * 9) * 2048;
    unsigned wr[8];
    {
        const uint4* s4 = (const uint4*)wbase + tid * 2;
        uint4 u0 = s4[0], u1 = s4[1];
        wr[0]=u0.x; wr[1]=u0.y; wr[2]=u0.z; wr[3]=u0.w;
        wr[4]=u1.x; wr[5]=u1.y; wr[6]=u1.z; wr[7]=u1.w;
    }
    __syncthreads();                                   // xs ready

    float acc[2][8][4];
    #pragma unroll
    for (int mt = 0; mt < 2; ++mt)
        #pragma unroll
        for (int nt = 0; nt < 8; ++nt)
            #pragma unroll
            for (int j = 0; j < 4; ++j) acc[mt][nt][j] = 0.f;

    const int wo = tid >> 2, ww0 = (tid & 3) * 8;      // wt STS mapping

    for (int j = 0; j < 9; ++j) {
        // store prefetched weights: wt[o][32 words], stride XW
        {
            unsigned* d = wt + wo * XW + ww0;
            #pragma unroll
            for (int i = 0; i < 8; ++i) d[i] = wr[i];
        }
        __syncthreads();                               // wt ready
        if (j < 8) {                                   // prefetch next tap
            const uint4* s4 = (const uint4*)(wbase + (size_t)(j+1)*2048) + tid*2;
            uint4 u0 = s4[0], u1 = s4[1];
            wr[0]=u0.x; wr[1]=u0.y; wr[2]=u0.z; wr[3]=u0.w;
            wr[4]=u1.x; wr[5]=u1.y; wr[6]=u1.z; wr[7]=u1.w;
        }

        const int ky = j / 3, kx = j % 3;
        const unsigned* arow = xs + ((warp + ky) * 34 + kx) * XW;

        #pragma unroll
        for (int kt = 0; kt < 4; ++kt) {
            const int kw = kt * 8 + tq;
            unsigned bf[8][2];
            #pragma unroll
            for (int nt = 0; nt < 8; ++nt) {
                const unsigned* wp = wt + (nt*8 + gq) * XW + kw;
                bf[nt][0] = wp[0];
                bf[nt][1] = wp[4];
            }
            #pragma unroll
            for (int mt = 0; mt < 2; ++mt) {
                const unsigned* ap = arow + (mt*16 + gq) * XW + kw;
                const unsigned a0 = ap[0];
                const unsigned a1 = ap[8*XW];
                const unsigned a2 = ap[4];
                const unsigned a3 = ap[8*XW + 4];
                #pragma unroll
                for (int nt = 0; nt < 8; ++nt)
                    mma_f16(acc[mt][nt], a0, a1, a2, a3, bf[nt][0], bf[nt][1]);
            }
        }
        __syncthreads();                               // MMA reads done
    }

    // ---- epilogue: residual add + store ----
    const int gy = y0 + warp;
    float* ob = out + (size_t)b * 64 * PLANE;
    #pragma unroll
    for (int mt = 0; mt < 2; ++mt) {
        const int px = x0 + mt*16 + gq;
        #pragma unroll
        for (int nt = 0; nt < 8; ++nt) {
            const int c0 = nt*8 + 2*tq;
            const size_t i00 = (size_t)c0 * PLANE + (size_t)gy * WW + px;
            ob[i00]             = xb[i00]             + acc[mt][nt][0];
            ob[i00 + PLANE]     = xb[i00 + PLANE]     + acc[mt][nt][1];
            ob[i00 + 8]         = xb[i00 + 8]         + acc[mt][nt][2];
            ob[i00 + PLANE + 8] = xb[i00 + PLANE + 8] + acc[mt][nt][3];
        }
    }
}

// ---------------------------------------------------------------------------
extern "C" void kernel_launch(void* const* d_in, const int* in_sizes, int n_in,
                              void* d_out, int out_size) {
    (void)in_sizes; (void)n_in; (void)out_size;
    const float* x     = (const float*)d_in[0];
    const float* vec   = (const float*)d_in[1];
    const float* gaff  = (const float*)d_in[2];
    const float* baff  = (const float*)d_in[3];
    const float* w1    = (const float*)d_in[4];
    const float* w2    = (const float*)d_in[5];
    const float* wconv = (const float*)d_in[6];
    float* out = (float*)d_out;

    style_kernel<<<NB, 256>>>(vec, w1, w2, wconv);

    const int smem = SMEM_WORDS * 4;
    cudaFuncSetAttribute(conv_kernel,
                         cudaFuncAttributeMaxDynamicSharedMemorySize, smem);
    dim3 grid(WW/32, HH/8, NB);
    conv_kernel<<<grid, 256, smem>>>(x, gaff, baff, out);
}

// round 5
// speedup vs baseline: 3.7124x; 1.0449x over previous
#include <cuda_runtime.h>
#include <cuda_fp16.h>
#include <cstdint>

#define HH 256
#define WW 256
#define NB 8
#define PLANE (HH*WW)
#define CIN 256
#define CHID 16

// per-sample demodulated conv weights, fp16 half2-packed, dense:
// [b][tap][o][32 words]  (word ip = channels 2ip, 2ip+1)
__device__ unsigned g_wmodh[NB * 9 * 64 * 32];

// ---------------------------------------------------------------------------
// Kernel 1: style MLP + weight modulation/demodulation -> fp16 packed weights
// ---------------------------------------------------------------------------
__global__ void style_kernel(const float* __restrict__ vec,
                             const float* __restrict__ w1,
                             const float* __restrict__ w2,
                             const float* __restrict__ wconv) {
    const int b = blockIdx.x, tid = threadIdx.x;
    __shared__ float sv[CIN], sh[CHID], ss[64];
    sv[tid] = vec[b*CIN + tid];
    __syncthreads();
    if (tid < CHID) {
        float acc = 0.f;
        #pragma unroll 8
        for (int c = 0; c < CIN; ++c) acc += sv[c] * w1[tid*CIN + c];
        sh[tid] = (acc > 0.f) ? acc : 0.1f * acc;     // LeakyReLU(0.1)
    }
    __syncthreads();
    if (tid < 64) {
        float acc = 0.f;
        #pragma unroll
        for (int j = 0; j < CHID; ++j) acc += sh[j] * w2[tid*CHID + j];
        ss[tid] = acc + 1.0f;                          // sty + 1
    }
    __syncthreads();
    const int warp = tid >> 5, lane = tid & 31;
    for (int o = warp; o < 64; o += 8) {
        float acc = 0.f;
        for (int idx = lane; idx < 576; idx += 32) {
            float v = wconv[o*576 + idx] * ss[idx / 9];
            acc += v * v;
        }
        #pragma unroll
        for (int s = 16; s; s >>= 1) acc += __shfl_xor_sync(0xffffffffu, acc, s);
        const float d = rsqrtf(acc + 1e-8f);
        for (int m = lane; m < 288; m += 32) {
            const int ip = m / 9, t = m % 9;
            const int i0 = 2 * ip;
            float v0 = wconv[o*576 + i0*9 + t]     * ss[i0]   * d;
            float v1 = wconv[o*576 + (i0+1)*9 + t] * ss[i0+1] * d;
            __half2 h = __floats2half2_rn(v0, v1);
            g_wmodh[(size_t)((b*9 + t)*64 + o)*32 + ip] = *(unsigned*)&h;
        }
    }
}

// ---------------------------------------------------------------------------
// Kernel 2: fused ChanNorm + modulated 3x3 conv (fp16 m16n8k16, ldmatrix) + res
// CTA tile: 8 rows x 32 cols x 64 out-ch.  8 warps, warp = one output row.
// xs: [pix = r*34+cc][44 words] half2; wt: double-buffered [2][64][44 words].
// Row stride 176B => LDSM 8-row fetches conflict-free (11i mod 8 permutation).
// ---------------------------------------------------------------------------
#define XW 44
#define NPX 340                          /* 10 halo rows * 34 halo cols */
#define OFF_WT (NPX*XW)                  /* 14960 words */
#define WTBUF  (64*XW)                   /* 2816 words per buffer */
#define OFF_G  (OFF_WT + 2*WTBUF)
#define OFF_B  (OFF_G + 64)
#define SMEM_WORDS (OFF_B + 64)          /* 20720 words = 82880 B */

__device__ __forceinline__ uint32_t smem_u32(const void* p) {
    uint32_t a;
    asm("{ .reg .u64 t; cvta.to.shared.u64 t, %1; cvt.u32.u64 %0, t; }" : "=r"(a) : "l"(p));
    return a;
}
__device__ __forceinline__ void ldsm_x4(unsigned r[4], uint32_t addr) {
    asm volatile("ldmatrix.sync.aligned.m8n8.x4.shared.b16 {%0,%1,%2,%3}, [%4];"
        : "=r"(r[0]), "=r"(r[1]), "=r"(r[2]), "=r"(r[3]) : "r"(addr));
}
__device__ __forceinline__ void mma_f16(float c[4],
                                        unsigned a0, unsigned a1,
                                        unsigned a2, unsigned a3,
                                        unsigned b0, unsigned b1) {
    asm volatile(
        "mma.sync.aligned.m16n8k16.row.col.f32.f16.f16.f32 "
        "{%0,%1,%2,%3}, {%4,%5,%6,%7}, {%8,%9}, {%0,%1,%2,%3};\n"
        : "+f"(c[0]), "+f"(c[1]), "+f"(c[2]), "+f"(c[3])
        : "r"(a0), "r"(a1), "r"(a2), "r"(a3), "r"(b0), "r"(b1));
}

__global__ __launch_bounds__(256, 2)
void conv_kernel(const float* __restrict__ x,
                 const float* __restrict__ gaff,
                 const float* __restrict__ baff,
                 float* __restrict__ out) {
    extern __shared__ unsigned sm[];
    unsigned* xs = sm;
    float* sg = (float*)(sm + OFF_G);
    float* sb = (float*)(sm + OFF_B);

    const int tid = threadIdx.x, warp = tid >> 5, lane = tid & 31;
    const int gq = lane >> 2, tq = lane & 3;
    const int x0 = blockIdx.x * 32, y0 = blockIdx.y * 8, b = blockIdx.z;
    const float* xb = x + (size_t)b * 64 * PLANE;

    if (tid < 64) { sg[tid] = gaff[tid]; sb[tid] = baff[tid]; }
    __syncthreads();

    // ---- ChanNorm halo tile -> fp16 half2 smem ----
    for (int p = tid; p < NPX; p += 256) {
        const int r = p / 34, cc = p % 34;
        const int gy = y0 - 1 + r, gx = x0 - 1 + cc;
        unsigned* dst = xs + p * XW;
        if (gy >= 0 && gy < HH && gx >= 0 && gx < WW) {
            const float* px = xb + (size_t)gy * WW + gx;
            float v[64], s = 0.f, s2 = 0.f;
            #pragma unroll
            for (int c = 0; c < 64; ++c) v[c] = px[(size_t)c * PLANE];
            #pragma unroll
            for (int c = 0; c < 64; ++c) { s += v[c]; s2 += v[c]*v[c]; }
            const float mean = s * (1.f/64.f);
            const float rstd = rsqrtf(s2 * (1.f/64.f) - mean*mean + 1e-5f);
            #pragma unroll
            for (int w = 0; w < 32; ++w) {
                float n0 = (v[2*w]   - mean) * rstd * sg[2*w]   + sb[2*w];
                float n1 = (v[2*w+1] - mean) * rstd * sg[2*w+1] + sb[2*w+1];
                __half2 h = __floats2half2_rn(n0, n1);
                dst[w] = *(unsigned*)&h;
            }
        } else {
            #pragma unroll
            for (int w = 0; w < 32; ++w) dst[w] = 0u;   // pad AFTER norm
        }
    }

    // ---- weight prefetch machinery ----
    const unsigned* wbase = g_wmodh + (size_t)(b * 9) * 2048;
    const int wo = tid >> 2, ww0 = (tid & 3) * 8;      // wt STS mapping
    unsigned wr[8];
    {   // tap 0 -> regs
        const uint4* s4 = (const uint4*)wbase + tid * 2;
        uint4 u0 = s4[0], u1 = s4[1];
        wr[0]=u0.x; wr[1]=u0.y; wr[2]=u0.z; wr[3]=u0.w;
        wr[4]=u1.x; wr[5]=u1.y; wr[6]=u1.z; wr[7]=u1.w;
    }
    {   // tap 0 -> wt buffer 0
        unsigned* d = sm + OFF_WT + wo * XW + ww0;
        #pragma unroll
        for (int i = 0; i < 8; ++i) d[i] = wr[i];
    }
    {   // tap 1 -> regs
        const uint4* s4 = (const uint4*)(wbase + 2048) + tid * 2;
        uint4 u0 = s4[0], u1 = s4[1];
        wr[0]=u0.x; wr[1]=u0.y; wr[2]=u0.z; wr[3]=u0.w;
        wr[4]=u1.x; wr[5]=u1.y; wr[6]=u1.z; wr[7]=u1.w;
    }

    // ---- ldmatrix base addresses (byte, shared space) ----
    const uint32_t xs_sa = smem_u32(sm);
    const uint32_t wt_sa = xs_sa + OFF_WT * 4;
    // A: lane -> pixel row (lane&15) + halo row (warp), k-half select (lane>>4)
    const uint32_t A0 = xs_sa + ((warp * 34 + (lane & 15)) * XW) * 4 + (lane >> 4) * 16;
    // B: lane -> n row ((lane&7) + ((lane>>4)&1)*8), word half ((lane>>3)&1)*4
    const uint32_t B0 = wt_sa + (((lane & 7) + ((lane >> 4) & 1) * 8) * XW) * 4
                              + ((lane >> 3) & 1) * 16;

    __syncthreads();                                   // xs + wt0 ready

    float acc[2][8][4];
    #pragma unroll
    for (int mt = 0; mt < 2; ++mt)
        #pragma unroll
        for (int nt = 0; nt < 8; ++nt)
            #pragma unroll
            for (int j = 0; j < 4; ++j) acc[mt][nt][j] = 0.f;

    for (int j = 0; j < 9; ++j) {
        const int ky = j / 3, kx = j % 3, s = j & 1;
        const uint32_t Abase = A0 + (uint32_t)((ky * 34 + kx) * XW) * 4;
        const uint32_t Bbase = B0 + (uint32_t)(s * WTBUF) * 4;

        #pragma unroll
        for (int kt = 0; kt < 4; ++kt) {
            const uint32_t ko = (uint32_t)kt * 32;
            unsigned a[2][4], bq[4][4];
            ldsm_x4(a[0], Abase + ko);
            ldsm_x4(a[1], Abase + ko + 16 * XW * 4);
            #pragma unroll
            for (int q = 0; q < 4; ++q)
                ldsm_x4(bq[q], Bbase + ko + (uint32_t)(q * 16 * XW) * 4);
            #pragma unroll
            for (int mt = 0; mt < 2; ++mt) {
                #pragma unroll
                for (int q = 0; q < 4; ++q) {
                    mma_f16(acc[mt][2*q],   a[mt][0], a[mt][1], a[mt][2], a[mt][3],
                            bq[q][0], bq[q][1]);
                    mma_f16(acc[mt][2*q+1], a[mt][0], a[mt][1], a[mt][2], a[mt][3],
                            bq[q][2], bq[q][3]);
                }
            }
        }

        if (j < 8) {
            // store prefetched tap j+1 into the other buffer
            unsigned* d = sm + OFF_WT + (s ^ 1) * WTBUF + wo * XW + ww0;
            #pragma unroll
            for (int i = 0; i < 8; ++i) d[i] = wr[i];
            if (j < 7) {   // prefetch tap j+2
                const uint4* s4 = (const uint4*)(wbase + (size_t)(j+2)*2048) + tid*2;
                uint4 u0 = s4[0], u1 = s4[1];
                wr[0]=u0.x; wr[1]=u0.y; wr[2]=u0.z; wr[3]=u0.w;
                wr[4]=u1.x; wr[5]=u1.y; wr[6]=u1.z; wr[7]=u1.w;
            }
        }
        __syncthreads();   // wt[s^1] visible; wt[s] free for overwrite next tap
    }

    // ---- epilogue: residual add + store ----
    const int gy = y0 + warp;
    float* ob = out + (size_t)b * 64 * PLANE;
    #pragma unroll
    for (int mt = 0; mt < 2; ++mt) {
        const int px = x0 + mt*16 + gq;
        #pragma unroll
        for (int nt = 0; nt < 8; ++nt) {
            const int c0 = nt*8 + 2*tq;
            const size_t i00 = (size_t)c0 * PLANE + (size_t)gy * WW + px;
            ob[i00]             = xb[i00]             + acc[mt][nt][0];
            ob[i00 + PLANE]     = xb[i00 + PLANE]     + acc[mt][nt][1];
            ob[i00 + 8]         = xb[i00 + 8]         + acc[mt][nt][2];
            ob[i00 + PLANE + 8] = xb[i00 + PLANE + 8] + acc[mt][nt][3];
        }
    }
}

// ---------------------------------------------------------------------------
extern "C" void kernel_launch(void* const* d_in, const int* in_sizes, int n_in,
                              void* d_out, int out_size) {
    (void)in_sizes; (void)n_in; (void)out_size;
    const float* x     = (const float*)d_in[0];
    const float* vec   = (const float*)d_in[1];
    const float* gaff  = (const float*)d_in[2];
    const float* baff  = (const float*)d_in[3];
    const float* w1    = (const float*)d_in[4];
    const float* w2    = (const float*)d_in[5];
    const float* wconv = (const float*)d_in[6];
    float* out = (float*)d_out;

    style_kernel<<<NB, 256>>>(vec, w1, w2, wconv);

    const int smem = SMEM_WORDS * 4;
    cudaFuncSetAttribute(conv_kernel,
                         cudaFuncAttributeMaxDynamicSharedMemorySize, smem);
    dim3 grid(WW/32, HH/8, NB);
    conv_kernel<<<grid, 256, smem>>>(x, gaff, baff, out);
}